// round 3
// baseline (speedup 1.0000x reference)
#include <cuda_runtime.h>
#include <cuda_fp16.h>
#include <math.h>
#include <float.h>

#ifndef M_PI
#define M_PI 3.14159265358979323846
#endif

// B=1, C_IN=32, D_OUT=32, P=2048, N=10, A=12
typedef unsigned long long ull;

// ---------------- packed f32x2 helpers (sm_103a) ---------------------------
__device__ __forceinline__ ull f2pk(float lo, float hi) {
    ull r; asm("mov.b64 %0,{%1,%2};" : "=l"(r) : "f"(lo), "f"(hi)); return r;
}
__device__ __forceinline__ void f2up(ull v, float& lo, float& hi) {
    asm("mov.b64 {%0,%1},%2;" : "=f"(lo), "=f"(hi) : "l"(v));
}
__device__ __forceinline__ ull ffma2(ull a, ull b, ull c) {
    ull d; asm("fma.rn.f32x2 %0,%1,%2,%3;" : "=l"(d) : "l"(a), "l"(b), "l"(c)); return d;
}
__device__ __forceinline__ ull fmul2(ull a, ull b) {
    ull d; asm("mul.rn.f32x2 %0,%1,%2;" : "=l"(d) : "l"(a), "l"(b)); return d;
}
__device__ __forceinline__ ull fadd2(ull a, ull b) {
    ull d; asm("add.rn.f32x2 %0,%1,%2;" : "=l"(d) : "l"(a), "l"(b)); return d;
}

// ---------------- device scratch ------------------------------------------
// g_ICO layout: VS[36] | SYMR[45] | VER[108]
__device__ float g_ICO[189];
__device__ float g_KDNT[12 * 3 * 32 * 12];     // [k][i][d][r]
__device__ float g_W2[416 * 96];               // [dk][c*3+j]
__device__ float g_BIASF[416];                 // [dk]
__device__ float g_FMST[96 * 2048];            // [c*3+i][p]  (transposed fm scratch)
__device__ __half g_KAH2[2048 * 12 * 32 * 12]; // [q][k][d][r]  fp16, 18.9MB
__device__ float g_CEN[32 * 2048 * 12];        // [d][p][r] center (k==12), fp32

#define VS_OFF   0
#define SYMR_OFF 36
#define VER_OFF  81

// ---------------- kernel B: input-dependent weight prep -------------------
__global__ void k_init_weights(const float* __restrict__ W,
                               const float* __restrict__ bias,
                               const float* __restrict__ dirs) {
    int t = blockIdx.x * blockDim.x + threadIdx.x;
    const float* SYMR = g_ICO + SYMR_OFF;
    const float* VER  = g_ICO + VER_OFF;
    if (t < 4608) {
        int d = t / 144, k = (t / 12) % 12, r = t % 12;
        float vv[3];
        if (k == 0)      { vv[0] = 0.f; vv[1] = 0.f; vv[2] = 1.f; }
        else if (k == 1) { vv[0] = 0.f; vv[1] = 0.f; vv[2] = -1.f; }
        else {
            int kk = (k - 2) / 5, m = (k - 2) % 5;
            float d0 = dirs[d*6 + kk*3 + 0];
            float d1 = dirs[d*6 + kk*3 + 1];
            float d2 = dirs[d*6 + kk*3 + 2];
            float nrm = sqrtf(d0*d0 + d1*d1 + d2*d2);
            float inv = 1.f / fmaxf(nrm, 1e-12f);
            d0 *= inv; d1 *= inv; d2 *= inv;
            for (int i = 0; i < 3; i++)
                vv[i] = SYMR[m*9+i*3+0]*d0 + SYMR[m*9+i*3+1]*d1 + SYMR[m*9+i*3+2]*d2;
        }
        for (int i = 0; i < 3; i++) {
            float o = VER[r*9+i*3+0]*vv[0] + VER[r*9+i*3+1]*vv[1] + VER[r*9+i*3+2]*vv[2];
            g_KDNT[((k*3 + i)*32 + d)*12 + r] = o;   // [k][i][d][r]
        }
    } else if (t < 4608 + 13312) {
        int id = t - 4608;
        int dk = id / 32, c = id % 32;
        int d = dk / 13, k = dk % 13;
        const float* wr = W + (d*32 + c)*9;
        float wf[3];
        if (k == 0)       { wf[0] = 0.f; wf[1] = 0.f; wf[2] = wr[0]; }
        else if (k == 1)  { wf[0] = 0.f; wf[1] = 0.f; wf[2] = -wr[1]; }
        else if (k == 12) { wf[0] = 0.f; wf[1] = 0.f; wf[2] = wr[8]; }
        else {
            int kk = (k - 2) / 5, m = (k - 2) % 5;
            float w0 = wr[2 + kk*3 + 0], w1 = wr[2 + kk*3 + 1], w2 = wr[2 + kk*3 + 2];
            for (int i = 0; i < 3; i++)
                wf[i] = SYMR[m*9+i*3+0]*w0 + SYMR[m*9+i*3+1]*w1 + SYMR[m*9+i*3+2]*w2;
        }
        g_W2[dk*96 + c*3 + 0] = wf[0];
        g_W2[dk*96 + c*3 + 1] = wf[1];
        g_W2[dk*96 + c*3 + 2] = wf[2];
    } else if (t < 4608 + 13312 + 416) {
        int dk = t - (4608 + 13312);
        int d = dk / 13, k = dk % 13;
        int col = (k == 0) ? 0 : (k == 1) ? 1 : (k <= 6) ? 2 : (k <= 11) ? 3 : 4;
        g_BIASF[dk] = bias[d*5 + col];
    }
}

// ---------------- kernel C: attention softmax + fm (warp per point) -------
__global__ void __launch_bounds__(256) k_fm(const float* __restrict__ fmap,
                                            const float* __restrict__ fcw,
                                            float* __restrict__ fm_out) {
    __shared__ float FCT[32*33];
    __shared__ float Xs[8][384];
    __shared__ float VSs[36];
    int tid = threadIdx.x;
    for (int i = tid; i < 1024; i += 256) {
        int r = i >> 5, cc = i & 31;
        FCT[cc*33 + r] = fcw[i];
    }
    if (tid < 36) VSs[tid] = g_ICO[VS_OFF + tid];
    int w = tid >> 5, lane = tid & 31;
    int p = blockIdx.x*8 + w;
    const float* src = &fmap[((size_t)lane*2048 + p)*12];
#pragma unroll
    for (int a = 0; a < 12; a++) Xs[w][a*32+lane] = src[a];
    __syncthreads();

    float L[12];
#pragma unroll
    for (int a = 0; a < 12; a++) L[a] = 0.f;
#pragma unroll
    for (int cc = 0; cc < 32; cc++) {
        float fc = FCT[cc*33 + lane];
#pragma unroll
        for (int a = 0; a < 12; a++) L[a] += Xs[w][a*32+cc] * fc;
    }
    float mx = L[0];
#pragma unroll
    for (int a = 1; a < 12; a++) mx = fmaxf(mx, L[a]);
    float e[12], s = 0.f;
#pragma unroll
    for (int a = 0; a < 12; a++) { e[a] = expf(L[a] - mx); s += e[a]; }
    float inv = 1.f / s;
    float f0 = 0.f, f1 = 0.f, f2 = 0.f;
#pragma unroll
    for (int a = 0; a < 12; a++) {
        float y = e[a] * inv * Xs[w][a*32+lane];
        f0 += y * VSs[a*3+0];
        f1 += y * VSs[a*3+1];
        f2 += y * VSs[a*3+2];
    }
    g_FMST[(lane*3 + 0)*2048 + p] = f0;
    g_FMST[(lane*3 + 1)*2048 + p] = f1;
    g_FMST[(lane*3 + 2)*2048 + p] = f2;
    fm_out[((size_t)lane*2048 + p)*3 + 0] = f0;
    fm_out[((size_t)lane*2048 + p)*3 + 1] = f1;
    fm_out[((size_t)lane*2048 + p)*3 + 2] = f2;
}

// ---------------- kernel D: ka via factored rotation, f32x2 packed ---------
// block 128 thr = 16 dk x 8 pslots; each thread: 1 dk x 4 points (2 f32x2 pairs)
__global__ void __launch_bounds__(128) k_ka() {
    __shared__ float2 Wsd[16][96];     // W duplicated into both lanes
    __shared__ float  Fs2[96][34];     // [c*3+i][pslot], pad 34 (even, 8B-align)
    __shared__ float2 verd[108];
    __shared__ float2 biasd[16];
    int tid = threadIdx.x;
    int dk0 = blockIdx.x * 16;
    int p0  = blockIdx.y * 32;
    for (int i = tid; i < 16*96; i += 128) {
        int row = i / 96, q = i % 96;
        float w = g_W2[(dk0+row)*96 + q];
        Wsd[row][q] = make_float2(w, w);
    }
    for (int i = tid; i < 96*32; i += 128) {
        int q = i >> 5, ps_ = i & 31;
        Fs2[q][ps_] = g_FMST[q*2048 + p0 + ps_];
    }
    if (tid < 108) { float v = g_ICO[VER_OFF + tid]; verd[tid] = make_float2(v, v); }
    if (tid < 16)  { float bv = g_BIASF[dk0 + tid];  biasd[tid] = make_float2(bv, bv); }
    __syncthreads();

    int dkl = tid & 15;
    int ps  = tid >> 4;
    ull G[2][9];
#pragma unroll
    for (int pr = 0; pr < 2; pr++)
#pragma unroll
        for (int q = 0; q < 9; q++) G[pr][q] = 0ULL;

#pragma unroll 4
    for (int c = 0; c < 32; c++) {
        ull w0 = *(const ull*)&Wsd[dkl][c*3+0];
        ull w1 = *(const ull*)&Wsd[dkl][c*3+1];
        ull w2 = *(const ull*)&Wsd[dkl][c*3+2];
#pragma unroll
        for (int pr = 0; pr < 2; pr++) {
            ull f0 = *(const ull*)&Fs2[c*3+0][ps*4 + pr*2];
            ull f1 = *(const ull*)&Fs2[c*3+1][ps*4 + pr*2];
            ull f2 = *(const ull*)&Fs2[c*3+2][ps*4 + pr*2];
            G[pr][0] = ffma2(w0, f0, G[pr][0]);
            G[pr][1] = ffma2(w0, f1, G[pr][1]);
            G[pr][2] = ffma2(w0, f2, G[pr][2]);
            G[pr][3] = ffma2(w1, f0, G[pr][3]);
            G[pr][4] = ffma2(w1, f1, G[pr][4]);
            G[pr][5] = ffma2(w1, f2, G[pr][5]);
            G[pr][6] = ffma2(w2, f0, G[pr][6]);
            G[pr][7] = ffma2(w2, f1, G[pr][7]);
            G[pr][8] = ffma2(w2, f2, G[pr][8]);
        }
    }

    int dk = dk0 + dkl;
    int d = dk / 13, k = dk % 13;
    ull bias2 = *(const ull*)&biasd[dkl];

#pragma unroll
    for (int pr = 0; pr < 2; pr++) {
        int pA = p0 + ps*4 + pr*2;
        int pB = pA + 1;
        // process r in chunks of 4 to cap live registers
#pragma unroll
        for (int g4 = 0; g4 < 3; g4++) {
            ull o4[4];
#pragma unroll
            for (int rr = 0; rr < 4; rr++) {
                int r = g4*4 + rr;
                ull s = bias2;
#pragma unroll
                for (int i = 0; i < 3; i++)
#pragma unroll
                    for (int j = 0; j < 3; j++)
                        s = ffma2(*(const ull*)&verd[r*9 + i*3 + j], G[pr][j*3 + i], s);
                o4[rr] = s;
            }
            float l0,h0,l1,h1,l2,h2,l3,h3;
            f2up(o4[0], l0, h0); f2up(o4[1], l1, h1);
            f2up(o4[2], l2, h2); f2up(o4[3], l3, h3);
            if (k == 12) {
                float4* cA = (float4*)&g_CEN[((size_t)d*2048 + pA)*12 + g4*4];
                float4* cB = (float4*)&g_CEN[((size_t)d*2048 + pB)*12 + g4*4];
                *cA = make_float4(l0, l1, l2, l3);
                *cB = make_float4(h0, h1, h2, h3);
            } else {
                // [q][k][d][r] halfs
                __half2* dA = (__half2*)&g_KAH2[(size_t)pA*4608 + k*384 + d*12 + g4*4];
                __half2* dB = (__half2*)&g_KAH2[(size_t)pB*4608 + k*384 + d*12 + g4*4];
                dA[0] = __floats2half2_rn(l0, l1);
                dA[1] = __floats2half2_rn(l2, l3);
                dB[0] = __floats2half2_rn(h0, h1);
                dB[1] = __floats2half2_rn(h2, h3);
            }
        }
    }
}

// ---------------- kernel E: theta + gather + max_n + sum_k + center -------
// block = 2 points x 96 (d,rg) threads; gathers lane-contiguous via [q][k][d][r]
__global__ void __launch_bounds__(192) k_final(const int* __restrict__ nbr,
                                               const float* __restrict__ verts,
                                               float* __restrict__ out) {
    __shared__ float2 nddup[2][10][3];
    __shared__ int qoffs[2][10];
    int tid = threadIdx.x;
    if (tid < 20) {
        int pp2 = tid / 10, n = tid % 10;
        int p2 = blockIdx.x*2 + pp2;
        int q = nbr[p2*10 + n];
        qoffs[pp2][n] = q * 9216;                  // byte offset of q-row
        float dx = verts[q*3+0] - verts[p2*3+0];
        float dy = verts[q*3+1] - verts[p2*3+1];
        float dz = verts[q*3+2] - verts[p2*3+2];
        float nrm = sqrtf(dx*dx + dy*dy + dz*dz);
        float inv = 1.f / fmaxf(nrm, 1e-12f);
        nddup[pp2][n][0] = make_float2(dx*inv, dx*inv);
        nddup[pp2][n][1] = make_float2(dy*inv, dy*inv);
        nddup[pp2][n][2] = make_float2(dz*inv, dz*inv);
    }
    __syncthreads();
    int pp = tid / 96;
    int u  = tid % 96;
    int d  = u / 3, rg = u % 3;
    int p  = blockIdx.x*2 + pp;

    float4 a4 = ((const float4*)&g_CEN[((size_t)d*2048 + p)*12])[rg];
    ull acc01 = f2pk(a4.x, a4.y);
    ull acc23 = f2pk(a4.z, a4.w);

    const char* base = ((const char*)g_KAH2) + (size_t)d*24 + rg*8;
    int qb[10];
#pragma unroll
    for (int n = 0; n < 10; n++) qb[n] = qoffs[pp][n];

    const __half2 zero2 = __half2half2(__ushort_as_half(0));

#pragma unroll 1
    for (int k = 0; k < 12; k++) {
        const float* ktb = &g_KDNT[k*1152 + d*12 + rg*4];   // [k][i][d][r]
        float4 c0 = *(const float4*)(ktb + 0);
        float4 c1 = *(const float4*)(ktb + 384);
        float4 c2 = *(const float4*)(ktb + 768);
        ull A01 = f2pk(c0.x, c0.y), A23 = f2pk(c0.z, c0.w);
        ull B01 = f2pk(c1.x, c1.y), B23 = f2pk(c1.z, c1.w);
        ull C01 = f2pk(c2.x, c2.y), C23 = f2pk(c2.z, c2.w);
        const char* kbase = base + k*768;

        __half2 m01, m23;
#pragma unroll
        for (int n = 0; n < 10; n++) {
            ull n0 = *(const ull*)&nddup[pp][n][0];
            ull n1 = *(const ull*)&nddup[pp][n][1];
            ull n2 = *(const ull*)&nddup[pp][n][2];
            ull t01 = ffma2(A01, n0, ffma2(B01, n1, fmul2(C01, n2)));
            ull t23 = ffma2(A23, n0, ffma2(B23, n1, fmul2(C23, n2)));
            float lo, hi;
            f2up(t01, lo, hi);
            __half2 h01 = __hmax2(__floats2half2_rn(lo, hi), zero2);
            f2up(t23, lo, hi);
            __half2 h23 = __hmax2(__floats2half2_rn(lo, hi), zero2);
            uint2 g = *(const uint2*)(kbase + qb[n]);
            __half2 v01 = __hmul2(h01, *(__half2*)&g.x);
            __half2 v23 = __hmul2(h23, *(__half2*)&g.y);
            if (n == 0) { m01 = v01; m23 = v23; }
            else        { m01 = __hmax2(m01, v01); m23 = __hmax2(m23, v23); }
        }
        float2 f01 = __half22float2(m01);
        float2 f23 = __half22float2(m23);
        acc01 = fadd2(acc01, f2pk(f01.x, f01.y));
        acc23 = fadd2(acc23, f2pk(f23.x, f23.y));
    }
    float a0, a1, a2, a3;
    f2up(acc01, a0, a1);
    f2up(acc23, a2, a3);
    ((float4*)&out[((size_t)d*2048 + p)*12])[rg] = make_float4(a0, a1, a2, a3);
}

// ---------------- host-side icosa constants --------------------------------
static float h_ico[189];
static bool h_ico_ready = false;

static void compute_icosa_host() {
    const double phi = (1.0 + sqrt(5.0)) * 0.5;
    double v[12][3];
    int idx = 0;
    double as_[2] = {1.0, -1.0};
    double bs_[2] = {phi, -phi};
    for (int ia = 0; ia < 2; ia++)
        for (int ib = 0; ib < 2; ib++) {
            double a = as_[ia], b = bs_[ib];
            v[idx][0] = 0.0; v[idx][1] = a;   v[idx][2] = b;   idx++;
            v[idx][0] = a;   v[idx][1] = b;   v[idx][2] = 0.0; idx++;
            v[idx][0] = b;   v[idx][1] = 0.0; v[idx][2] = a;   idx++;
        }
    for (int i = 0; i < 12; i++) {
        double n = sqrt(v[i][0]*v[i][0] + v[i][1]*v[i][1] + v[i][2]*v[i][2]);
        for (int j = 0; j < 3; j++) { v[i][j] /= n; h_ico[VS_OFF + i*3+j] = (float)v[i][j]; }
    }
    for (int m = 0; m < 5; m++) {
        double t = 2.0 * M_PI * (double)m / 5.0;
        double ct = cos(t), st = sin(t);
        double R[3][3] = {{ct, -st, 0.0}, {st, ct, 0.0}, {0.0, 0.0, 1.0}};
        for (int i = 0; i < 3; i++)
            for (int j = 0; j < 3; j++)
                h_ico[SYMR_OFF + m*9 + i*3 + j] = (float)R[i][j];
    }
    for (int r = 0; r < 12; r++) {
        double c = v[r][2];
        double axx = -v[r][1], axy = v[r][0];
        double s = sqrt(axx*axx + axy*axy);
        double R[3][3];
        if (s < 1e-9) {
            for (int i = 0; i < 3; i++) for (int j = 0; j < 3; j++) R[i][j] = 0.0;
            R[0][0] = 1.0;
            R[1][1] = (c > 0) ? 1.0 : -1.0;
            R[2][2] = (c > 0) ? 1.0 : -1.0;
        } else {
            double kx = axx / s, ky = axy / s;
            double K[3][3] = {{0, 0, ky}, {0, 0, -kx}, {-ky, kx, 0}};
            double KK[3][3];
            for (int i = 0; i < 3; i++)
                for (int j = 0; j < 3; j++) {
                    double acc = 0.0;
                    for (int q = 0; q < 3; q++) acc += K[i][q]*K[q][j];
                    KK[i][j] = acc;
                }
            for (int i = 0; i < 3; i++)
                for (int j = 0; j < 3; j++)
                    R[i][j] = (i == j ? 1.0 : 0.0) + s*K[i][j] + (1.0 - c)*KK[i][j];
        }
        for (int i = 0; i < 3; i++)
            for (int j = 0; j < 3; j++)
                h_ico[VER_OFF + r*9 + i*3 + j] = (float)R[i][j];
    }
}

// ---------------- launch ----------------------------------------------------
extern "C" void kernel_launch(void* const* d_in, const int* in_sizes, int n_in,
                              void* d_out, int out_size) {
    const int*   nbr   = (const int*)d_in[0];
    const float* verts = (const float*)d_in[1];
    const float* fmap  = (const float*)d_in[2];
    const float* W     = (const float*)d_in[3];
    const float* bias  = (const float*)d_in[4];
    const float* dirs  = (const float*)d_in[5];
    const float* fcw   = (const float*)d_in[6];
    float* out    = (float*)d_out;              // (1,32,2048,12)
    float* fm_out = out + 32*2048*12;           // (1,32,2048,3)

    if (!h_ico_ready) { compute_icosa_host(); h_ico_ready = true; }
    cudaMemcpyToSymbolAsync(g_ICO, h_ico, sizeof(h_ico), 0,
                            cudaMemcpyHostToDevice, 0);

    k_init_weights<<<72, 256>>>(W, bias, dirs);
    k_fm<<<256, 256>>>(fmap, fcw, fm_out);
    k_ka<<<dim3(26, 64), 128>>>();
    k_final<<<1024, 192>>>(nbr, verts, out);
}

// round 4
// speedup vs baseline: 1.2828x; 1.2828x over previous
#include <cuda_runtime.h>
#include <cuda_fp16.h>
#include <math.h>
#include <float.h>

#ifndef M_PI
#define M_PI 3.14159265358979323846
#endif

// B=1, C_IN=32, D_OUT=32, P=2048, N=10, A=12
typedef unsigned long long ull;

// ---------------- packed f32x2 helpers (sm_103a) ---------------------------
__device__ __forceinline__ ull f2pk(float lo, float hi) {
    ull r; asm("mov.b64 %0,{%1,%2};" : "=l"(r) : "f"(lo), "f"(hi)); return r;
}
__device__ __forceinline__ void f2up(ull v, float& lo, float& hi) {
    asm("mov.b64 {%0,%1},%2;" : "=f"(lo), "=f"(hi) : "l"(v));
}
__device__ __forceinline__ ull ffma2(ull a, ull b, ull c) {
    ull d; asm("fma.rn.f32x2 %0,%1,%2,%3;" : "=l"(d) : "l"(a), "l"(b), "l"(c)); return d;
}

// ---------------- device scratch ------------------------------------------
// g_ICO layout: VS[36] | SYMR[45] | VER[108]
__device__ float g_ICO[189];
__device__ float g_KDNT[12 * 3 * 32 * 12];     // [k][i][d][r]
__device__ float g_W2[416 * 96];               // [dk][c*3+j]
__device__ float g_BIASF[416];                 // [dk]
__device__ float g_FMST[96 * 2048];            // [c*3+i][p]
__device__ __half g_KAH2[2048 * 12 * 32 * 12]; // [q][k][d][r]  fp16, 18.9MB
__device__ float g_CEN[32 * 2048 * 12];        // [d][p][r] center (k==12), fp32

#define VS_OFF   0
#define SYMR_OFF 36
#define VER_OFF  81

// ---------------- kernel B: input-dependent weight prep -------------------
__global__ void k_init_weights(const float* __restrict__ W,
                               const float* __restrict__ bias,
                               const float* __restrict__ dirs) {
    int t = blockIdx.x * blockDim.x + threadIdx.x;
    const float* SYMR = g_ICO + SYMR_OFF;
    const float* VER  = g_ICO + VER_OFF;
    if (t < 4608) {
        int d = t / 144, k = (t / 12) % 12, r = t % 12;
        float vv[3];
        if (k == 0)      { vv[0] = 0.f; vv[1] = 0.f; vv[2] = 1.f; }
        else if (k == 1) { vv[0] = 0.f; vv[1] = 0.f; vv[2] = -1.f; }
        else {
            int kk = (k - 2) / 5, m = (k - 2) % 5;
            float d0 = dirs[d*6 + kk*3 + 0];
            float d1 = dirs[d*6 + kk*3 + 1];
            float d2 = dirs[d*6 + kk*3 + 2];
            float nrm = sqrtf(d0*d0 + d1*d1 + d2*d2);
            float inv = 1.f / fmaxf(nrm, 1e-12f);
            d0 *= inv; d1 *= inv; d2 *= inv;
            for (int i = 0; i < 3; i++)
                vv[i] = SYMR[m*9+i*3+0]*d0 + SYMR[m*9+i*3+1]*d1 + SYMR[m*9+i*3+2]*d2;
        }
        for (int i = 0; i < 3; i++) {
            float o = VER[r*9+i*3+0]*vv[0] + VER[r*9+i*3+1]*vv[1] + VER[r*9+i*3+2]*vv[2];
            g_KDNT[((k*3 + i)*32 + d)*12 + r] = o;
        }
    } else if (t < 4608 + 13312) {
        int id = t - 4608;
        int dk = id / 32, c = id % 32;
        int d = dk / 13, k = dk % 13;
        const float* wr = W + (d*32 + c)*9;
        float wf[3];
        if (k == 0)       { wf[0] = 0.f; wf[1] = 0.f; wf[2] = wr[0]; }
        else if (k == 1)  { wf[0] = 0.f; wf[1] = 0.f; wf[2] = -wr[1]; }
        else if (k == 12) { wf[0] = 0.f; wf[1] = 0.f; wf[2] = wr[8]; }
        else {
            int kk = (k - 2) / 5, m = (k - 2) % 5;
            float w0 = wr[2 + kk*3 + 0], w1 = wr[2 + kk*3 + 1], w2 = wr[2 + kk*3 + 2];
            for (int i = 0; i < 3; i++)
                wf[i] = SYMR[m*9+i*3+0]*w0 + SYMR[m*9+i*3+1]*w1 + SYMR[m*9+i*3+2]*w2;
        }
        g_W2[dk*96 + c*3 + 0] = wf[0];
        g_W2[dk*96 + c*3 + 1] = wf[1];
        g_W2[dk*96 + c*3 + 2] = wf[2];
    } else if (t < 4608 + 13312 + 416) {
        int dk = t - (4608 + 13312);
        int d = dk / 13, k = dk % 13;
        int col = (k == 0) ? 0 : (k == 1) ? 1 : (k <= 6) ? 2 : (k <= 11) ? 3 : 4;
        g_BIASF[dk] = bias[d*5 + col];
    }
}

// ---------------- kernel C: attention softmax + fm (warp per point) -------
__global__ void __launch_bounds__(256) k_fm(const float* __restrict__ fmap,
                                            const float* __restrict__ fcw,
                                            float* __restrict__ fm_out) {
    __shared__ float FCT[32*33];
    __shared__ float Xs[8][384];
    __shared__ float VSs[36];
    int tid = threadIdx.x;
    for (int i = tid; i < 1024; i += 256) {
        int r = i >> 5, cc = i & 31;
        FCT[cc*33 + r] = fcw[i];
    }
    if (tid < 36) VSs[tid] = g_ICO[VS_OFF + tid];
    int w = tid >> 5, lane = tid & 31;
    int p = blockIdx.x*8 + w;
    const float* src = &fmap[((size_t)lane*2048 + p)*12];
#pragma unroll
    for (int a = 0; a < 12; a++) Xs[w][a*32+lane] = src[a];
    __syncthreads();

    float L[12];
#pragma unroll
    for (int a = 0; a < 12; a++) L[a] = 0.f;
#pragma unroll
    for (int cc = 0; cc < 32; cc++) {
        float fc = FCT[cc*33 + lane];
#pragma unroll
        for (int a = 0; a < 12; a++) L[a] += Xs[w][a*32+cc] * fc;
    }
    float mx = L[0];
#pragma unroll
    for (int a = 1; a < 12; a++) mx = fmaxf(mx, L[a]);
    float e[12], s = 0.f;
#pragma unroll
    for (int a = 0; a < 12; a++) { e[a] = expf(L[a] - mx); s += e[a]; }
    float inv = 1.f / s;
    float f0 = 0.f, f1 = 0.f, f2 = 0.f;
#pragma unroll
    for (int a = 0; a < 12; a++) {
        float y = e[a] * inv * Xs[w][a*32+lane];
        f0 += y * VSs[a*3+0];
        f1 += y * VSs[a*3+1];
        f2 += y * VSs[a*3+2];
    }
    g_FMST[(lane*3 + 0)*2048 + p] = f0;
    g_FMST[(lane*3 + 1)*2048 + p] = f1;
    g_FMST[(lane*3 + 2)*2048 + p] = f2;
    fm_out[((size_t)lane*2048 + p)*3 + 0] = f0;
    fm_out[((size_t)lane*2048 + p)*3 + 1] = f1;
    fm_out[((size_t)lane*2048 + p)*3 + 2] = f2;
}

// ---------------- kernel D: ka via factored rotation, f32x2 packed ---------
// block 128 thr = 16 dk x 8 pslots; each thread: 1 dk x 4 points (2 f32x2 pairs)
// Wsd padded to 97 float2/row: stride 194 words == 2 mod 32 -> conflict-free.
__global__ void __launch_bounds__(128) k_ka() {
    __shared__ float2 Wsd[16][97];
    __shared__ float  Fs2[96][34];
    __shared__ float2 verd[108];
    __shared__ float2 biasd[16];
    int tid = threadIdx.x;
    int dk0 = blockIdx.x * 16;
    int p0  = blockIdx.y * 32;
    for (int i = tid; i < 16*96; i += 128) {
        int row = i / 96, q = i % 96;
        float w = g_W2[(dk0+row)*96 + q];
        Wsd[row][q] = make_float2(w, w);
    }
    for (int i = tid; i < 96*32; i += 128) {
        int q = i >> 5, ps_ = i & 31;
        Fs2[q][ps_] = g_FMST[q*2048 + p0 + ps_];
    }
    if (tid < 108) { float v = g_ICO[VER_OFF + tid]; verd[tid] = make_float2(v, v); }
    if (tid < 16)  { float bv = g_BIASF[dk0 + tid];  biasd[tid] = make_float2(bv, bv); }
    __syncthreads();

    int dkl = tid & 15;
    int ps  = tid >> 4;
    ull G[2][9];
#pragma unroll
    for (int pr = 0; pr < 2; pr++)
#pragma unroll
        for (int q = 0; q < 9; q++) G[pr][q] = 0ULL;

#pragma unroll 4
    for (int c = 0; c < 32; c++) {
        ull w0 = *(const ull*)&Wsd[dkl][c*3+0];
        ull w1 = *(const ull*)&Wsd[dkl][c*3+1];
        ull w2 = *(const ull*)&Wsd[dkl][c*3+2];
#pragma unroll
        for (int pr = 0; pr < 2; pr++) {
            ull f0 = *(const ull*)&Fs2[c*3+0][ps*4 + pr*2];
            ull f1 = *(const ull*)&Fs2[c*3+1][ps*4 + pr*2];
            ull f2 = *(const ull*)&Fs2[c*3+2][ps*4 + pr*2];
            G[pr][0] = ffma2(w0, f0, G[pr][0]);
            G[pr][1] = ffma2(w0, f1, G[pr][1]);
            G[pr][2] = ffma2(w0, f2, G[pr][2]);
            G[pr][3] = ffma2(w1, f0, G[pr][3]);
            G[pr][4] = ffma2(w1, f1, G[pr][4]);
            G[pr][5] = ffma2(w1, f2, G[pr][5]);
            G[pr][6] = ffma2(w2, f0, G[pr][6]);
            G[pr][7] = ffma2(w2, f1, G[pr][7]);
            G[pr][8] = ffma2(w2, f2, G[pr][8]);
        }
    }

    int dk = dk0 + dkl;
    int d = dk / 13, k = dk % 13;
    ull bias2 = *(const ull*)&biasd[dkl];

#pragma unroll
    for (int pr = 0; pr < 2; pr++) {
        int pA = p0 + ps*4 + pr*2;
        int pB = pA + 1;
#pragma unroll
        for (int g4 = 0; g4 < 3; g4++) {
            ull o4[4];
#pragma unroll
            for (int rr = 0; rr < 4; rr++) {
                int r = g4*4 + rr;
                ull s = bias2;
#pragma unroll
                for (int i = 0; i < 3; i++)
#pragma unroll
                    for (int j = 0; j < 3; j++)
                        s = ffma2(*(const ull*)&verd[r*9 + i*3 + j], G[pr][j*3 + i], s);
                o4[rr] = s;
            }
            float l0,h0,l1,h1,l2,h2,l3,h3;
            f2up(o4[0], l0, h0); f2up(o4[1], l1, h1);
            f2up(o4[2], l2, h2); f2up(o4[3], l3, h3);
            if (k == 12) {
                float4* cA = (float4*)&g_CEN[((size_t)d*2048 + pA)*12 + g4*4];
                float4* cB = (float4*)&g_CEN[((size_t)d*2048 + pB)*12 + g4*4];
                *cA = make_float4(l0, l1, l2, l3);
                *cB = make_float4(h0, h1, h2, h3);
            } else {
                __half2* dA = (__half2*)&g_KAH2[(size_t)pA*4608 + k*384 + d*12 + g4*4];
                __half2* dB = (__half2*)&g_KAH2[(size_t)pB*4608 + k*384 + d*12 + g4*4];
                dA[0] = __floats2half2_rn(l0, l1);
                dA[1] = __floats2half2_rn(l2, l3);
                dB[0] = __floats2half2_rn(h0, h1);
                dB[1] = __floats2half2_rn(h2, h3);
            }
        }
    }
}

// ---------------- kernel E: theta + gather + max_n + sum_k + center -------
// block = 4 points x 96 (d,rg); scalar fp32 theta, half2 gather math
__global__ void __launch_bounds__(384) k_final(const int* __restrict__ nbr,
                                               const float* __restrict__ verts,
                                               float* __restrict__ out) {
    __shared__ float nds[4][30];     // [pp][n*3+i]
    __shared__ int qoffs[4][10];
    int tid = threadIdx.x;
    if (tid < 40) {
        int pp2 = tid / 10, n = tid % 10;
        int p2 = blockIdx.x*4 + pp2;
        int q = nbr[p2*10 + n];
        qoffs[pp2][n] = q * 9216;            // byte offset of q-row in g_KAH2
        float dx = verts[q*3+0] - verts[p2*3+0];
        float dy = verts[q*3+1] - verts[p2*3+1];
        float dz = verts[q*3+2] - verts[p2*3+2];
        float nrm = sqrtf(dx*dx + dy*dy + dz*dz);
        float inv = 1.f / fmaxf(nrm, 1e-12f);
        nds[pp2][n*3+0] = dx*inv;
        nds[pp2][n*3+1] = dy*inv;
        nds[pp2][n*3+2] = dz*inv;
    }
    __syncthreads();
    int pp = tid / 96;
    int u  = tid % 96;
    int d  = u / 3, rg = u % 3;
    int p  = blockIdx.x*4 + pp;

    float nd[30];
#pragma unroll
    for (int i = 0; i < 30; i++) nd[i] = nds[pp][i];
    int qb[10];
#pragma unroll
    for (int n = 0; n < 10; n++) qb[n] = qoffs[pp][n];

    float4 a4 = ((const float4*)&g_CEN[((size_t)d*2048 + p)*12])[rg];
    float acc0 = a4.x, acc1 = a4.y, acc2 = a4.z, acc3 = a4.w;

    const char* base = ((const char*)g_KAH2) + (size_t)d*24 + rg*8;
    const __half2 zero2 = __half2half2(__ushort_as_half(0));

#pragma unroll 1
    for (int k = 0; k < 12; k++) {
        const float* ktb = &g_KDNT[k*1152 + d*12 + rg*4];   // [k][i][d][r]
        float4 c0 = *(const float4*)(ktb + 0);
        float4 c1 = *(const float4*)(ktb + 384);
        float4 c2 = *(const float4*)(ktb + 768);
        const char* kbase = base + k*768;

        __half2 m01, m23;
#pragma unroll
        for (int n = 0; n < 10; n++) {
            float nx = nd[n*3+0], ny = nd[n*3+1], nz = nd[n*3+2];
            float t0 = fmaf(c0.x, nx, fmaf(c1.x, ny, c2.x*nz));
            float t1 = fmaf(c0.y, nx, fmaf(c1.y, ny, c2.y*nz));
            float t2 = fmaf(c0.z, nx, fmaf(c1.z, ny, c2.z*nz));
            float t3 = fmaf(c0.w, nx, fmaf(c1.w, ny, c2.w*nz));
            __half2 h01 = __hmax2(__floats2half2_rn(t0, t1), zero2);
            __half2 h23 = __hmax2(__floats2half2_rn(t2, t3), zero2);
            uint2 g = *(const uint2*)(kbase + qb[n]);
            __half2 v01 = __hmul2(h01, *(__half2*)&g.x);
            __half2 v23 = __hmul2(h23, *(__half2*)&g.y);
            if (n == 0) { m01 = v01; m23 = v23; }
            else        { m01 = __hmax2(m01, v01); m23 = __hmax2(m23, v23); }
        }
        float2 f01 = __half22float2(m01);
        float2 f23 = __half22float2(m23);
        acc0 += f01.x; acc1 += f01.y;
        acc2 += f23.x; acc3 += f23.y;
    }
    ((float4*)&out[((size_t)d*2048 + p)*12])[rg] = make_float4(acc0, acc1, acc2, acc3);
}

// ---------------- host-side icosa constants --------------------------------
static float h_ico[189];
static bool h_ico_ready = false;

static void compute_icosa_host() {
    const double phi = (1.0 + sqrt(5.0)) * 0.5;
    double v[12][3];
    int idx = 0;
    double as_[2] = {1.0, -1.0};
    double bs_[2] = {phi, -phi};
    for (int ia = 0; ia < 2; ia++)
        for (int ib = 0; ib < 2; ib++) {
            double a = as_[ia], b = bs_[ib];
            v[idx][0] = 0.0; v[idx][1] = a;   v[idx][2] = b;   idx++;
            v[idx][0] = a;   v[idx][1] = b;   v[idx][2] = 0.0; idx++;
            v[idx][0] = b;   v[idx][1] = 0.0; v[idx][2] = a;   idx++;
        }
    for (int i = 0; i < 12; i++) {
        double n = sqrt(v[i][0]*v[i][0] + v[i][1]*v[i][1] + v[i][2]*v[i][2]);
        for (int j = 0; j < 3; j++) { v[i][j] /= n; h_ico[VS_OFF + i*3+j] = (float)v[i][j]; }
    }
    for (int m = 0; m < 5; m++) {
        double t = 2.0 * M_PI * (double)m / 5.0;
        double ct = cos(t), st = sin(t);
        double R[3][3] = {{ct, -st, 0.0}, {st, ct, 0.0}, {0.0, 0.0, 1.0}};
        for (int i = 0; i < 3; i++)
            for (int j = 0; j < 3; j++)
                h_ico[SYMR_OFF + m*9 + i*3 + j] = (float)R[i][j];
    }
    for (int r = 0; r < 12; r++) {
        double c = v[r][2];
        double axx = -v[r][1], axy = v[r][0];
        double s = sqrt(axx*axx + axy*axy);
        double R[3][3];
        if (s < 1e-9) {
            for (int i = 0; i < 3; i++) for (int j = 0; j < 3; j++) R[i][j] = 0.0;
            R[0][0] = 1.0;
            R[1][1] = (c > 0) ? 1.0 : -1.0;
            R[2][2] = (c > 0) ? 1.0 : -1.0;
        } else {
            double kx = axx / s, ky = axy / s;
            double K[3][3] = {{0, 0, ky}, {0, 0, -kx}, {-ky, kx, 0}};
            double KK[3][3];
            for (int i = 0; i < 3; i++)
                for (int j = 0; j < 3; j++) {
                    double acc = 0.0;
                    for (int q = 0; q < 3; q++) acc += K[i][q]*K[q][j];
                    KK[i][j] = acc;
                }
            for (int i = 0; i < 3; i++)
                for (int j = 0; j < 3; j++)
                    R[i][j] = (i == j ? 1.0 : 0.0) + s*K[i][j] + (1.0 - c)*KK[i][j];
        }
        for (int i = 0; i < 3; i++)
            for (int j = 0; j < 3; j++)
                h_ico[VER_OFF + r*9 + i*3 + j] = (float)R[i][j];
    }
}

// ---------------- launch ----------------------------------------------------
extern "C" void kernel_launch(void* const* d_in, const int* in_sizes, int n_in,
                              void* d_out, int out_size) {
    const int*   nbr   = (const int*)d_in[0];
    const float* verts = (const float*)d_in[1];
    const float* fmap  = (const float*)d_in[2];
    const float* W     = (const float*)d_in[3];
    const float* bias  = (const float*)d_in[4];
    const float* dirs  = (const float*)d_in[5];
    const float* fcw   = (const float*)d_in[6];
    float* out    = (float*)d_out;              // (1,32,2048,12)
    float* fm_out = out + 32*2048*12;           // (1,32,2048,3)

    if (!h_ico_ready) { compute_icosa_host(); h_ico_ready = true; }
    cudaMemcpyToSymbolAsync(g_ICO, h_ico, sizeof(h_ico), 0,
                            cudaMemcpyHostToDevice, 0);

    k_init_weights<<<72, 256>>>(W, bias, dirs);
    k_fm<<<256, 256>>>(fmap, fcw, fm_out);
    k_ka<<<dim3(26, 64), 128>>>();
    k_final<<<512, 384>>>(nbr, verts, out);
}